// round 1
// baseline (speedup 1.0000x reference)
#include <cuda_runtime.h>
#include <stdint.h>

// ---------------------------------------------------------------------------
// Problem constants
// ---------------------------------------------------------------------------
#define B_ 64
#define S_ 400
#define E_ 512
#define H_ 1024
#define A_ 512
#define V_ 50257

// Output layout: flat concat of (logits, h1, c1, attn_weights, input_feed_new)
#define O_LOGITS ((size_t)0)
#define O_H1     ((size_t)B_ * V_)
#define O_C1     (O_H1 + (size_t)B_ * H_)
#define O_ATTN   (O_C1 + (size_t)B_ * H_)
#define O_IFN    (O_ATTN + (size_t)S_ * B_)

// ---------------------------------------------------------------------------
// Device scratch (static allocation only — no cudaMalloc allowed)
// ---------------------------------------------------------------------------
__device__ float g_x[B_ * (E_ + H_)];            // [64, 1536]  emb | input_feed
__device__ float g_gates[B_ * 4 * H_];           // [64, 4096]
__device__ float g_query[B_ * A_];               // [64, 512]
__device__ float g_keys[(size_t)S_ * B_ * A_];   // [25600, 512] ~52 MB
__device__ float g_align[S_ * B_];               // [400*64]
__device__ float g_cat[B_ * 2 * H_];             // [64, 2048]  h1 | ctx

// ---------------------------------------------------------------------------
// tf32 helpers
// ---------------------------------------------------------------------------
__device__ __forceinline__ float f2tf32(float x) {
    uint32_t u;
    asm("cvt.rna.tf32.f32 %0, %1;" : "=r"(u) : "f"(x));
    return __uint_as_float(u);
}

__device__ __forceinline__ void mma_tf32(float* d, const uint32_t* a, const uint32_t* b) {
    asm volatile(
        "mma.sync.aligned.m16n8k8.row.col.f32.tf32.tf32.f32 "
        "{%0,%1,%2,%3}, {%4,%5,%6,%7}, {%8,%9}, {%0,%1,%2,%3};\n"
        : "+f"(d[0]), "+f"(d[1]), "+f"(d[2]), "+f"(d[3])
        : "r"(a[0]), "r"(a[1]), "r"(a[2]), "r"(a[3]),
          "r"(b[0]), "r"(b[1]));
}

// ---------------------------------------------------------------------------
// Generic TN GEMM: C[M,N] = A[M,K] @ B[N,K]^T (+bias[n]) (+= old C if accum)
// Block tile 64(M) x 128(N), 4 warps, each warp 64x32 (4x4 m16n8k8 tiles).
// Requires M % 64 == 0, K % 16 == 0. N arbitrary (guarded).
// ---------------------------------------------------------------------------
#define GBM 64
#define GBN 128
#define GBK 16

__global__ __launch_bounds__(128)
void gemm_tn_kernel(const float* __restrict__ A, const float* __restrict__ Bw,
                    float* __restrict__ C, int M, int N, int K,
                    const float* __restrict__ bias, int accum)
{
    __shared__ float As[GBM][GBK + 4];
    __shared__ float Bs[GBN][GBK + 4];

    const int tid  = threadIdx.x;
    const int wid  = tid >> 5;
    const int lane = tid & 31;
    const int g    = lane >> 2;   // groupID
    const int tg   = lane & 3;    // threadID_in_group
    const int bn0  = blockIdx.x * GBN;
    const int bm0  = blockIdx.y * GBM;

    float acc[4][4][4];
#pragma unroll
    for (int mt = 0; mt < 4; mt++)
#pragma unroll
        for (int nt = 0; nt < 4; nt++)
#pragma unroll
            for (int e = 0; e < 4; e++) acc[mt][nt][e] = 0.f;

    for (int kt = 0; kt < K; kt += GBK) {
        // Load A tile: 64 rows x 16 cols = 256 float4, 128 threads -> 2 each
#pragma unroll
        for (int i = 0; i < 2; i++) {
            const int idx = tid + i * 128;
            const int r = idx >> 2;
            const int c = (idx & 3) << 2;
            const float4 v = *reinterpret_cast<const float4*>(
                A + (size_t)(bm0 + r) * K + kt + c);
            As[r][c + 0] = f2tf32(v.x);
            As[r][c + 1] = f2tf32(v.y);
            As[r][c + 2] = f2tf32(v.z);
            As[r][c + 3] = f2tf32(v.w);
        }
        // Load B tile: 128 rows x 16 cols = 512 float4 -> 4 each (guard rows >= N)
#pragma unroll
        for (int i = 0; i < 4; i++) {
            const int idx = tid + i * 128;
            const int r = idx >> 2;
            const int c = (idx & 3) << 2;
            float4 v = make_float4(0.f, 0.f, 0.f, 0.f);
            if (bn0 + r < N)
                v = *reinterpret_cast<const float4*>(
                    Bw + (size_t)(bn0 + r) * K + kt + c);
            Bs[r][c + 0] = f2tf32(v.x);
            Bs[r][c + 1] = f2tf32(v.y);
            Bs[r][c + 2] = f2tf32(v.z);
            Bs[r][c + 3] = f2tf32(v.w);
        }
        __syncthreads();

#pragma unroll
        for (int kk = 0; kk < GBK; kk += 8) {
            uint32_t af[4][4];
            uint32_t bf[4][2];
#pragma unroll
            for (int mt = 0; mt < 4; mt++) {
                const int m = mt * 16;
                af[mt][0] = __float_as_uint(As[m + g    ][kk + tg    ]);
                af[mt][1] = __float_as_uint(As[m + g + 8][kk + tg    ]);
                af[mt][2] = __float_as_uint(As[m + g    ][kk + tg + 4]);
                af[mt][3] = __float_as_uint(As[m + g + 8][kk + tg + 4]);
            }
#pragma unroll
            for (int nt = 0; nt < 4; nt++) {
                const int n = wid * 32 + nt * 8;
                bf[nt][0] = __float_as_uint(Bs[n + g][kk + tg    ]);
                bf[nt][1] = __float_as_uint(Bs[n + g][kk + tg + 4]);
            }
#pragma unroll
            for (int mt = 0; mt < 4; mt++)
#pragma unroll
                for (int nt = 0; nt < 4; nt++)
                    mma_tf32(acc[mt][nt], af[mt], bf[nt]);
        }
        __syncthreads();
    }

    // Epilogue
#pragma unroll
    for (int mt = 0; mt < 4; mt++) {
        const int r0 = bm0 + mt * 16 + g;
#pragma unroll
        for (int nt = 0; nt < 4; nt++) {
            const int c0 = bn0 + wid * 32 + nt * 8 + 2 * tg;
#pragma unroll
            for (int e = 0; e < 4; e++) {
                const int rr = r0 + (e >> 1) * 8;
                const int cc = c0 + (e & 1);
                if (cc < N) {
                    float v = acc[mt][nt][e];
                    if (bias) v += bias[cc];
                    size_t off = (size_t)rr * N + cc;
                    if (accum) v += C[off];
                    C[off] = v;
                }
            }
        }
    }
}

// ---------------------------------------------------------------------------
// Small kernels
// ---------------------------------------------------------------------------
__global__ void build_x_kernel(const int* __restrict__ tokens,
                               const float* __restrict__ emb_table,
                               const float* __restrict__ input_feed)
{
    const int b = blockIdx.x;
    const float* erow = emb_table + (size_t)tokens[b] * E_;
    for (int j = threadIdx.x; j < E_ + H_; j += blockDim.x) {
        g_x[b * (E_ + H_) + j] = (j < E_) ? erow[j] : input_feed[b * H_ + (j - E_)];
    }
}

__global__ void lstm_kernel(const float* __restrict__ c0,
                            float* __restrict__ h1, float* __restrict__ c1)
{
    const int idx = blockIdx.x * blockDim.x + threadIdx.x;  // 64*1024
    const int b = idx >> 10;
    const int h = idx & 1023;
    const float* gr = g_gates + b * 4 * H_;
    const float gi = gr[h];
    const float gf = gr[H_ + h];
    const float gg = gr[2 * H_ + h];
    const float go = gr[3 * H_ + h];
    const float si = 1.f / (1.f + expf(-gi));
    const float sf = 1.f / (1.f + expf(-gf));
    const float so = 1.f / (1.f + expf(-go));
    const float c = sf * c0[idx] + si * tanhf(gg);
    const float hh = so * tanhf(c);
    c1[idx] = c;
    h1[idx] = hh;
    g_cat[b * 2 * H_ + h] = hh;  // left half of [h1 | ctx]
}

// alignment[r] = sum_a align_w[a] * tanh(keys[r,a] + query[r%64, a])
__global__ void align_kernel(const float* __restrict__ align_w)
{
    const int wid  = threadIdx.x >> 5;
    const int lane = threadIdx.x & 31;
    const int r = blockIdx.x * 8 + wid;
    const int b = r & (B_ - 1);
    const float* krow = g_keys + (size_t)r * A_;
    const float* qrow = g_query + b * A_;
    float s = 0.f;
#pragma unroll
    for (int i = 0; i < A_ / 32; i++) {
        const int a = lane + i * 32;
        s += align_w[a] * tanhf(krow[a] + qrow[a]);
    }
#pragma unroll
    for (int o = 16; o; o >>= 1) s += __shfl_xor_sync(0xffffffffu, s, o);
    if (lane == 0) g_align[r] = s;
}

// softmax over s (dim 0) for each of 64 columns
__global__ void softmax_kernel(float* __restrict__ w)
{
    __shared__ float red[128];
    const int b = blockIdx.x;
    const int tid = threadIdx.x;
    float m = -1e30f;
    for (int s = tid; s < S_; s += 128) m = fmaxf(m, g_align[s * B_ + b]);
    red[tid] = m; __syncthreads();
    for (int o = 64; o; o >>= 1) { if (tid < o) red[tid] = fmaxf(red[tid], red[tid + o]); __syncthreads(); }
    m = red[0]; __syncthreads();
    float sum = 0.f;
    for (int s = tid; s < S_; s += 128) sum += expf(g_align[s * B_ + b] - m);
    red[tid] = sum; __syncthreads();
    for (int o = 64; o; o >>= 1) { if (tid < o) red[tid] += red[tid + o]; __syncthreads(); }
    const float inv = 1.f / red[0];
    for (int s = tid; s < S_; s += 128)
        w[s * B_ + b] = expf(g_align[s * B_ + b] - m) * inv;
}

// ctx[b,h] = sum_s w[s,b] * enc[s,b,h]  -> right half of g_cat
__global__ void ctx_kernel(const float* __restrict__ w, const float* __restrict__ enc)
{
    const int b = blockIdx.x;
    const int h = blockIdx.y * 256 + threadIdx.x;
    float acc = 0.f;
#pragma unroll 4
    for (int s = 0; s < S_; s++)
        acc += w[s * B_ + b] * enc[((size_t)s * B_ + b) * H_ + h];
    g_cat[b * 2 * H_ + H_ + h] = acc;
}

// ---------------------------------------------------------------------------
// kernel_launch
// ---------------------------------------------------------------------------
extern "C" void kernel_launch(void* const* d_in, const int* in_sizes, int n_in,
                              void* d_out, int out_size)
{
    (void)in_sizes; (void)n_in; (void)out_size;
    const int*   tokens     = (const int*)  d_in[0];
    const float* h0         = (const float*)d_in[1];   // [1,64,1024]
    const float* c0         = (const float*)d_in[2];
    const float* enc        = (const float*)d_in[3];   // [400,64,1024]
    const float* input_feed = (const float*)d_in[4];
    const float* emb_table  = (const float*)d_in[5];
    const float* W_ih       = (const float*)d_in[6];   // [4096,1536]
    const float* W_hh       = (const float*)d_in[7];   // [4096,1024]
    const float* b_ih       = (const float*)d_in[8];
    const float* b_hh       = (const float*)d_in[9];
    const float* attnm_w    = (const float*)d_in[10];  // [512,1024]
    const float* attnq_w    = (const float*)d_in[11];  // [512,1024]
    const float* attnq_b    = (const float*)d_in[12];
    const float* align_w    = (const float*)d_in[13];  // [1,512]
    const float* lin_out_w  = (const float*)d_in[14];  // [1024,2048]
    const float* lin_out_b  = (const float*)d_in[15];
    const float* out_w      = (const float*)d_in[16];  // [50257,1024]
    const float* out_b      = (const float*)d_in[17];

    float* out = (float*)d_out;
    float* out_logits = out + O_LOGITS;
    float* out_h1     = out + O_H1;
    float* out_c1     = out + O_C1;
    float* out_attn   = out + O_ATTN;
    float* out_ifn    = out + O_IFN;

    float* x    = nullptr;  float* gates = nullptr; float* query = nullptr;
    float* keys = nullptr;  float* cat   = nullptr;
    cudaGetSymbolAddress((void**)&x,     g_x);
    cudaGetSymbolAddress((void**)&gates, g_gates);
    cudaGetSymbolAddress((void**)&query, g_query);
    cudaGetSymbolAddress((void**)&keys,  g_keys);
    cudaGetSymbolAddress((void**)&cat,   g_cat);

    // 1. x = [emb(tokens) | input_feed]   [64, 1536]
    build_x_kernel<<<B_, 256>>>(tokens, emb_table, input_feed);

    // 2. gates = x @ W_ih^T + b_ih        [64, 4096]
    gemm_tn_kernel<<<dim3((4 * H_) / GBN, 1), 128>>>(
        x, W_ih, gates, B_, 4 * H_, E_ + H_, b_ih, 0);
    // 3. gates += h0 @ W_hh^T + b_hh
    gemm_tn_kernel<<<dim3((4 * H_) / GBN, 1), 128>>>(
        h0, W_hh, gates, B_, 4 * H_, H_, b_hh, 1);

    // 4. LSTM cell -> h1, c1 (also fills left half of cat)
    lstm_kernel<<<(B_ * H_) / 256, 256>>>(c0, out_h1, out_c1);

    // 5. query = h1 @ attnq_w^T + attnq_b   [64, 512]
    gemm_tn_kernel<<<dim3(A_ / GBN, 1), 128>>>(
        out_h1, attnq_w, query, B_, A_, H_, attnq_b, 0);

    // 6. keys = enc @ attnm_w^T             [25600, 512]
    gemm_tn_kernel<<<dim3(A_ / GBN, (S_ * B_) / GBM), 128>>>(
        enc, attnm_w, keys, S_ * B_, A_, H_, nullptr, 0);

    // 7. alignment[r] = align_w . tanh(keys[r] + query[b])
    align_kernel<<<(S_ * B_) / 8, 256>>>(align_w);

    // 8. softmax over s -> attn weights (output region)
    softmax_kernel<<<B_, 128>>>(out_attn);

    // 9. ctx -> right half of cat
    ctx_kernel<<<dim3(B_, H_ / 256), 256>>>(out_attn, enc);

    // 10. input_feed_new = cat @ lin_out_w^T + lin_out_b   [64, 1024]
    gemm_tn_kernel<<<dim3(H_ / GBN, 1), 128>>>(
        cat, lin_out_w, out_ifn, B_, H_, 2 * H_, lin_out_b, 0);

    // 11. logits = ifn @ out_w^T + out_b    [64, 50257]
    gemm_tn_kernel<<<dim3((V_ + GBN - 1) / GBN, 1), 128>>>(
        out_ifn, out_w, out_logits, B_, V_, H_, out_b, 0);
}

// round 2
// speedup vs baseline: 2.1089x; 2.1089x over previous
#include <cuda_runtime.h>
#include <stdint.h>

// ---------------------------------------------------------------------------
// Problem constants
// ---------------------------------------------------------------------------
#define B_ 64
#define S_ 400
#define E_ 512
#define H_ 1024
#define A_ 512
#define V_ 50257
#define SB_ (S_ * B_)   // 25600

// Output layout: flat concat of (logits, h1, c1, attn_weights, input_feed_new)
#define O_LOGITS ((size_t)0)
#define O_H1     ((size_t)B_ * V_)
#define O_C1     (O_H1 + (size_t)B_ * H_)
#define O_ATTN   (O_C1 + (size_t)B_ * H_)
#define O_IFN    (O_ATTN + (size_t)SB_)

// ---------------------------------------------------------------------------
// Device scratch (static only — no cudaMalloc allowed)
// ---------------------------------------------------------------------------
__device__ float g_x[B_ * (E_ + H_)];          // [64,1536]
__device__ float g_gp[5 * B_ * 4 * H_];        // gate GEMM split-K partials
__device__ float g_qp[8 * B_ * A_];            // query split-K partials
__device__ float g_query[B_ * A_];             // [64,512]
__device__ float g_ifp[4 * B_ * H_];           // lin_out split-K partials
__device__ float g_alignp[4 * SB_];            // per-Nblock align partials
__device__ float g_cat[B_ * 2 * H_];           // [64,2048] h1 | ctx

// ---------------------------------------------------------------------------
// PTX helpers
// ---------------------------------------------------------------------------
__device__ __forceinline__ void cp16(uint32_t dst, const void* src, int szbytes) {
    asm volatile("cp.async.cg.shared.global [%0], [%1], 16, %2;\n"
                 :: "r"(dst), "l"(src), "r"(szbytes));
}
__device__ __forceinline__ void cp_commit() {
    asm volatile("cp.async.commit_group;\n");
}
template <int N>
__device__ __forceinline__ void cp_wait() {
    asm volatile("cp.async.wait_group %0;\n" :: "n"(N));
}
__device__ __forceinline__ uint32_t tf32_of(float v) {
    uint32_t u;
    asm("cvt.rna.tf32.f32 %0, %1;" : "=r"(u) : "f"(v));
    return u;
}
__device__ __forceinline__ float tanh_fast(float x) {
    float y;
    asm("tanh.approx.f32 %0, %1;" : "=f"(y) : "f"(x));
    return y;
}
__device__ __forceinline__ void mma_tf32(float* d, const uint32_t* a, const uint32_t* b) {
    asm volatile(
        "mma.sync.aligned.m16n8k8.row.col.f32.tf32.tf32.f32 "
        "{%0,%1,%2,%3}, {%4,%5,%6,%7}, {%8,%9}, {%0,%1,%2,%3};\n"
        : "+f"(d[0]), "+f"(d[1]), "+f"(d[2]), "+f"(d[3])
        : "r"(a[0]), "r"(a[1]), "r"(a[2]), "r"(a[3]),
          "r"(b[0]), "r"(b[1]));
}

// ---------------------------------------------------------------------------
// TN GEMM: C[M,N] = A[M,K] @ B[N,K]^T, tf32 tensor cores, cp.async 2-stage.
// 256 threads, block tile BM x 128 x 32. Warp grid 2(M) x 4(N).
// Split-K: gridDim.z slices of length klen; slice z writes C + z*M*N.
// FUSE: Bahdanau align epilogue (no C write):
//   alignp[xblk*M + row] = sum_n align_w[n] * tanh(acc[row][n] + query[row&63][n])
// ---------------------------------------------------------------------------
#define BN 128
#define BK 32
#define PAD 36   // BK + 4 (keeps 16B alignment, conflict-free frag loads)

template <int BM, bool FUSE>
__global__ __launch_bounds__(256, 2)
void gemm_tc(const float* __restrict__ A, const float* __restrict__ Bw,
             float* __restrict__ C, int M, int N, int K, int klen,
             const float* __restrict__ bias,
             const float* __restrict__ query,
             const float* __restrict__ align_w,
             float* __restrict__ alignp)
{
    constexpr int MT = BM / 32;               // m16-tiles per warp (2 or 4)
    extern __shared__ float smem[];
    float* As = smem;                          // [2][BM][PAD]
    float* Bs = smem + 2 * BM * PAD;           // [2][BN][PAD]

    const int tid  = threadIdx.x;
    const int wid  = tid >> 5;
    const int lane = tid & 31;
    const int wm   = wid >> 2;                 // 0..1
    const int wn   = wid & 3;                  // 0..3
    const int g    = lane >> 2;                // 0..7
    const int tg   = lane & 3;                 // 0..3
    const int bn0  = blockIdx.x * BN;
    const int bm0  = blockIdx.y * BM;
    const int kbase = blockIdx.z * klen;

    const uint32_t sA = (uint32_t)__cvta_generic_to_shared(As);
    const uint32_t sB = (uint32_t)__cvta_generic_to_shared(Bs);

    float acc[MT][4][4];
#pragma unroll
    for (int mt = 0; mt < MT; mt++)
#pragma unroll
        for (int nt = 0; nt < 4; nt++)
#pragma unroll
            for (int e = 0; e < 4; e++) acc[mt][nt][e] = 0.f;

    auto load_stage = [&](int buf, int kt0) {
#pragma unroll
        for (int i = 0; i < BM / 32; i++) {
            const int idx = tid + i * 256;
            const int r = idx >> 3;
            const int kc = (idx & 7) * 4;
            const float* src = A + (size_t)(bm0 + r) * K + kbase + kt0 + kc;
            cp16(sA + ((buf * BM + r) * PAD + kc) * 4, src, 16);
        }
#pragma unroll
        for (int i = 0; i < 4; i++) {
            const int idx = tid + i * 256;
            const int r = idx >> 3;
            const int kc = (idx & 7) * 4;
            const float* src = Bw + (size_t)(bn0 + r) * K + kbase + kt0 + kc;
            cp16(sB + ((buf * BN + r) * PAD + kc) * 4, src,
                 (bn0 + r) < N ? 16 : 0);
        }
    };

    const int NKT = klen / BK;
    int buf = 0;
    load_stage(0, 0);
    cp_commit();

    for (int kt = 0; kt < NKT; kt++) {
        if (kt + 1 < NKT) {
            load_stage(buf ^ 1, (kt + 1) * BK);
            cp_commit();
            cp_wait<1>();
        } else {
            cp_wait<0>();
        }
        __syncthreads();

        const float* Ab = As + (size_t)(buf * BM + wm * MT * 16) * PAD;
        const float* Bb = Bs + (size_t)(buf * BN + wn * 32) * PAD;
#pragma unroll
        for (int kk = 0; kk < BK; kk += 8) {
            uint32_t af[MT][4];
            uint32_t bf[4][2];
#pragma unroll
            for (int mt = 0; mt < MT; mt++) {
                const float* p = Ab + mt * 16 * PAD + kk;
                af[mt][0] = tf32_of(p[(g)     * PAD + tg]);
                af[mt][1] = tf32_of(p[(g + 8) * PAD + tg]);
                af[mt][2] = tf32_of(p[(g)     * PAD + tg + 4]);
                af[mt][3] = tf32_of(p[(g + 8) * PAD + tg + 4]);
            }
#pragma unroll
            for (int nt = 0; nt < 4; nt++) {
                const float* p = Bb + nt * 8 * PAD + kk;
                bf[nt][0] = tf32_of(p[g * PAD + tg]);
                bf[nt][1] = tf32_of(p[g * PAD + tg + 4]);
            }
#pragma unroll
            for (int mt = 0; mt < MT; mt++)
#pragma unroll
                for (int nt = 0; nt < 4; nt++)
                    mma_tf32(acc[mt][nt], af[mt], bf[nt]);
        }
        __syncthreads();
        buf ^= 1;
    }

    if (!FUSE) {
        float* Cout = C + (size_t)blockIdx.z * M * N;
#pragma unroll
        for (int mt = 0; mt < MT; mt++) {
#pragma unroll
            for (int nt = 0; nt < 4; nt++) {
#pragma unroll
                for (int e = 0; e < 4; e++) {
                    const int r = bm0 + wm * MT * 16 + mt * 16 + g + (e >> 1) * 8;
                    const int c = bn0 + wn * 32 + nt * 8 + 2 * tg + (e & 1);
                    if (c < N) {
                        float v = acc[mt][nt][e];
                        if (bias) v += bias[c];
                        Cout[(size_t)r * N + c] = v;
                    }
                }
            }
        }
    } else {
        // Bahdanau epilogue: per-row partial sum over this block's 128 N-cols.
        float rs[MT][2];
#pragma unroll
        for (int mt = 0; mt < MT; mt++) { rs[mt][0] = 0.f; rs[mt][1] = 0.f; }
#pragma unroll
        for (int mt = 0; mt < MT; mt++) {
#pragma unroll
            for (int nt = 0; nt < 4; nt++) {
#pragma unroll
                for (int e = 0; e < 4; e++) {
                    const int rloc = wm * MT * 16 + mt * 16 + g + (e >> 1) * 8;
                    const int c = bn0 + wn * 32 + nt * 8 + 2 * tg + (e & 1);
                    const int b = (bm0 + rloc) & (B_ - 1);
                    const float t = tanh_fast(acc[mt][nt][e] + query[b * A_ + c]);
                    rs[mt][e >> 1] += align_w[c] * t;
                }
            }
        }
        // reduce across the 4 tg-lanes of each row group (deterministic)
#pragma unroll
        for (int mt = 0; mt < MT; mt++) {
#pragma unroll
            for (int hh = 0; hh < 2; hh++) {
                float v = rs[mt][hh];
                v += __shfl_xor_sync(0xffffffffu, v, 1);
                v += __shfl_xor_sync(0xffffffffu, v, 2);
                rs[mt][hh] = v;
            }
        }
        __syncthreads();                       // done with mainloop smem
        float* red = smem;                     // [BM][4] row partials per wn
        if (tg == 0) {
#pragma unroll
            for (int mt = 0; mt < MT; mt++) {
#pragma unroll
                for (int hh = 0; hh < 2; hh++) {
                    const int rloc = wm * MT * 16 + mt * 16 + g + hh * 8;
                    red[rloc * 4 + wn] = rs[mt][hh];
                }
            }
        }
        __syncthreads();
        if (tid < BM) {
            const float s = red[tid * 4] + red[tid * 4 + 1] +
                            red[tid * 4 + 2] + red[tid * 4 + 3];
            alignp[(size_t)blockIdx.x * M + bm0 + tid] = s;
        }
    }
}

// ---------------------------------------------------------------------------
// Small kernels
// ---------------------------------------------------------------------------
__global__ void build_x_kernel(const int* __restrict__ tokens,
                               const float* __restrict__ emb_table,
                               const float* __restrict__ input_feed)
{
    const int b = blockIdx.x;
    const float* erow = emb_table + (size_t)tokens[b] * E_;
    for (int j = threadIdx.x; j < E_ + H_; j += blockDim.x)
        g_x[b * (E_ + H_) + j] = (j < E_) ? erow[j] : input_feed[b * H_ + (j - E_)];
}

// Reduce 5 gate partial slices + biases, apply LSTM cell.
__global__ void lstm_kernel(const float* __restrict__ c0,
                            const float* __restrict__ b_ih,
                            const float* __restrict__ b_hh,
                            float* __restrict__ h1, float* __restrict__ c1)
{
    const int idx = blockIdx.x * blockDim.x + threadIdx.x;  // 64*1024
    const int b = idx >> 10;
    const int h = idx & 1023;
    const size_t base = (size_t)b * 4 * H_;
    float gi = b_ih[h]           + b_hh[h];
    float gf = b_ih[H_ + h]      + b_hh[H_ + h];
    float gg = b_ih[2 * H_ + h]  + b_hh[2 * H_ + h];
    float go = b_ih[3 * H_ + h]  + b_hh[3 * H_ + h];
#pragma unroll
    for (int z = 0; z < 5; z++) {
        const float* p = g_gp + (size_t)z * B_ * 4 * H_ + base;
        gi += p[h];
        gf += p[H_ + h];
        gg += p[2 * H_ + h];
        go += p[3 * H_ + h];
    }
    const float si = 1.f / (1.f + expf(-gi));
    const float sf = 1.f / (1.f + expf(-gf));
    const float so = 1.f / (1.f + expf(-go));
    const float c = sf * c0[idx] + si * tanhf(gg);
    const float hh = so * tanhf(c);
    c1[idx] = c;
    h1[idx] = hh;
    g_cat[b * 2 * H_ + h] = hh;
}

__global__ void qreduce_kernel(const float* __restrict__ attnq_b)
{
    const int i = blockIdx.x * 256 + threadIdx.x;  // 64*512
    const int c = i & (A_ - 1);
    float s = attnq_b[c];
#pragma unroll
    for (int z = 0; z < 8; z++) s += g_qp[(size_t)z * B_ * A_ + i];
    g_query[i] = s;
}

__global__ void ifreduce_kernel(const float* __restrict__ lin_out_b,
                                float* __restrict__ out_ifn)
{
    const int i = blockIdx.x * 256 + threadIdx.x;  // 64*1024
    const int c = i & (H_ - 1);
    float s = lin_out_b[c];
#pragma unroll
    for (int z = 0; z < 4; z++) s += g_ifp[(size_t)z * B_ * H_ + i];
    out_ifn[i] = s;
}

// softmax over s for each batch column; alignment = sum of 4 N-block partials
__global__ void softmax_kernel(float* __restrict__ w)
{
    __shared__ float vals[S_];
    __shared__ float red[128];
    const int b = blockIdx.x;
    const int tid = threadIdx.x;
    for (int s = tid; s < S_; s += 128) {
        vals[s] = g_alignp[s * B_ + b] +
                  g_alignp[SB_ + s * B_ + b] +
                  g_alignp[2 * SB_ + s * B_ + b] +
                  g_alignp[3 * SB_ + s * B_ + b];
    }
    __syncthreads();
    float m = -1e30f;
    for (int s = tid; s < S_; s += 128) m = fmaxf(m, vals[s]);
    red[tid] = m; __syncthreads();
    for (int o = 64; o; o >>= 1) {
        if (tid < o) red[tid] = fmaxf(red[tid], red[tid + o]);
        __syncthreads();
    }
    m = red[0]; __syncthreads();
    float sum = 0.f;
    for (int s = tid; s < S_; s += 128) sum += expf(vals[s] - m);
    red[tid] = sum; __syncthreads();
    for (int o = 64; o; o >>= 1) {
        if (tid < o) red[tid] += red[tid + o];
        __syncthreads();
    }
    const float inv = 1.f / red[0];
    for (int s = tid; s < S_; s += 128)
        w[s * B_ + b] = expf(vals[s] - m) * inv;
}

// ctx[b,h] = sum_s w[s,b] * enc[s,b,h] -> right half of g_cat
__global__ void ctx_kernel(const float* __restrict__ w, const float* __restrict__ enc)
{
    const int b = blockIdx.x;
    const int h = blockIdx.y * 256 + threadIdx.x;
    float acc = 0.f;
#pragma unroll 4
    for (int s = 0; s < S_; s++)
        acc += w[s * B_ + b] * enc[((size_t)s * B_ + b) * H_ + h];
    g_cat[b * 2 * H_ + H_ + h] = acc;
}

// ---------------------------------------------------------------------------
// kernel_launch
// ---------------------------------------------------------------------------
extern "C" void kernel_launch(void* const* d_in, const int* in_sizes, int n_in,
                              void* d_out, int out_size)
{
    (void)in_sizes; (void)n_in; (void)out_size;
    const int*   tokens     = (const int*)  d_in[0];
    const float* h0         = (const float*)d_in[1];
    const float* c0         = (const float*)d_in[2];
    const float* enc        = (const float*)d_in[3];
    const float* input_feed = (const float*)d_in[4];
    const float* emb_table  = (const float*)d_in[5];
    const float* W_ih       = (const float*)d_in[6];
    const float* W_hh       = (const float*)d_in[7];
    const float* b_ih       = (const float*)d_in[8];
    const float* b_hh       = (const float*)d_in[9];
    const float* attnm_w    = (const float*)d_in[10];
    const float* attnq_w    = (const float*)d_in[11];
    const float* attnq_b    = (const float*)d_in[12];
    const float* align_w    = (const float*)d_in[13];
    const float* lin_out_w  = (const float*)d_in[14];
    const float* lin_out_b  = (const float*)d_in[15];
    const float* out_w      = (const float*)d_in[16];
    const float* out_b      = (const float*)d_in[17];

    float* out = (float*)d_out;
    float* out_logits = out + O_LOGITS;
    float* out_h1     = out + O_H1;
    float* out_c1     = out + O_C1;
    float* out_attn   = out + O_ATTN;
    float* out_ifn    = out + O_IFN;

    float *x, *gp, *qp, *query, *ifp, *alignp, *cat;
    cudaGetSymbolAddress((void**)&x,      g_x);
    cudaGetSymbolAddress((void**)&gp,     g_gp);
    cudaGetSymbolAddress((void**)&qp,     g_qp);
    cudaGetSymbolAddress((void**)&query,  g_query);
    cudaGetSymbolAddress((void**)&ifp,    g_ifp);
    cudaGetSymbolAddress((void**)&alignp, g_alignp);
    cudaGetSymbolAddress((void**)&cat,    g_cat);

    const int smem128 = 2 * (128 + BN) * PAD * 4;  // 73728 B
    const int smem64  = 2 * (64 + BN) * PAD * 4;   // 55296 B
    cudaFuncSetAttribute((const void*)gemm_tc<128, true>,
                         cudaFuncAttributeMaxDynamicSharedMemorySize, smem128);
    cudaFuncSetAttribute((const void*)gemm_tc<64, false>,
                         cudaFuncAttributeMaxDynamicSharedMemorySize, smem64);

    // 1. x = [emb | input_feed]
    build_x_kernel<<<B_, 256>>>(tokens, emb_table, input_feed);

    // 2. gates partials: x@W_ih^T (3 K-slices) and h0@W_hh^T (2 K-slices)
    gemm_tc<64, false><<<dim3(32, 1, 3), 256, smem64>>>(
        x, W_ih, gp, B_, 4 * H_, E_ + H_, 512, nullptr, nullptr, nullptr, nullptr);
    gemm_tc<64, false><<<dim3(32, 1, 2), 256, smem64>>>(
        h0, W_hh, gp + 3 * (size_t)B_ * 4 * H_, B_, 4 * H_, H_, 512,
        nullptr, nullptr, nullptr, nullptr);

    // 3. gate reduce + LSTM cell
    lstm_kernel<<<(B_ * H_) / 256, 256>>>(c0, b_ih, b_hh, out_h1, out_c1);

    // 4. query partials (8 K-slices) + reduce
    gemm_tc<64, false><<<dim3(4, 1, 8), 256, smem64>>>(
        out_h1, attnq_w, qp, B_, A_, H_, 128, nullptr, nullptr, nullptr, nullptr);
    qreduce_kernel<<<(B_ * A_) / 256, 256>>>(attnq_b);

    // 5. keys GEMM fused with align epilogue (no keys materialization)
    gemm_tc<128, true><<<dim3(4, SB_ / 128, 1), 256, smem128>>>(
        enc, attnm_w, nullptr, SB_, A_, H_, H_, nullptr, query, align_w, alignp);

    // 6. softmax over s (sums the 4 align partials)
    softmax_kernel<<<B_, 128>>>(out_attn);

    // 7. context
    ctx_kernel<<<dim3(B_, H_ / 256), 256>>>(out_attn, enc);

    // 8. input_feed_new partials (4 K-slices) + reduce
    gemm_tc<64, false><<<dim3(8, 1, 4), 256, smem64>>>(
        cat, lin_out_w, ifp, B_, H_, 2 * H_, 512, nullptr, nullptr, nullptr, nullptr);
    ifreduce_kernel<<<(B_ * H_) / 256, 256>>>(lin_out_b, out_ifn);

    // 9. logits
    gemm_tc<64, false><<<dim3((V_ + BN - 1) / BN, 1, 1), 256, smem64>>>(
        out_ifn, out_w, out_logits, B_, V_, H_, H_, out_b,
        nullptr, nullptr, nullptr);
}